// round 7
// baseline (speedup 1.0000x reference)
#include <cuda_runtime.h>
#include <cstdint>

#define NODES_MAX 50048
#define EDGES_MAX 800000
#define IN_C  128
#define HID_C 128
#define OUT_C 64
#define NCHUNK 4

// ---------------- device scratch ----------------
__device__ float  g_h   [(size_t)NODES_MAX * HID_C];   // x @ W1
__device__ float  g_agg [(size_t)NODES_MAX * HID_C];   // relu(gather + b1)
__device__ float  g_h2  [(size_t)NODES_MAX * OUT_C];   // agg @ W2
__device__ int    g_idx_is64;

// CSR-by-dst scratch
__device__ int    g_counts [NODES_MAX];
__device__ int    g_partial[NODES_MAX];
__device__ int    g_bsum   [64];
__device__ int    g_row_off[NODES_MAX + 1];
__device__ int    g_cursor [NODES_MAX];
__device__ float2 g_csr_sw [EDGES_MAX];   // .x = src idx (int bits), .y = weight

// ---------------- zero counts + detect idx dtype (merged) ----------------
__global__ void zero_detect_kernel(const int* __restrict__ ei_words, int n) {
    int i = blockIdx.x * blockDim.x + threadIdx.x;
    if (i < n) g_counts[i] = 0;
    if (blockIdx.x == 0 && threadIdx.x < 32) {
        int lane = threadIdx.x;
        int bad = 0;
        for (int k = lane; k < 1024; k += 32)
            if (ei_words[2 * k + 1] != 0) bad = 1;
        bad = __any_sync(0xffffffffu, bad);
        if (lane == 0) g_idx_is64 = bad ? 0 : 1;
    }
}

__device__ __forceinline__ void load_sd(const int* __restrict__ ei, int e, int E,
                                        int is64, int& s, int& d) {
    if (is64) { s = ei[2 * e]; d = ei[2 * E + 2 * e]; }
    else      { s = ei[e];     d = ei[E + e]; }
}

__device__ __forceinline__ int load_d(const int* __restrict__ ei, int e, int E, int is64) {
    return is64 ? ei[2 * E + 2 * e] : ei[E + e];
}

// ---------------- CSR build ----------------
__global__ void hist_kernel(const int* __restrict__ ei, int E) {
    int base = (blockIdx.x * blockDim.x + threadIdx.x) * 4;
    int is64 = g_idx_is64;
    int d0 = -1, d1 = -1, d2 = -1, d3 = -1;
    if (base + 0 < E) d0 = load_d(ei, base + 0, E, is64);
    if (base + 1 < E) d1 = load_d(ei, base + 1, E, is64);
    if (base + 2 < E) d2 = load_d(ei, base + 2, E, is64);
    if (base + 3 < E) d3 = load_d(ei, base + 3, E, is64);
    if (d0 >= 0) atomicAdd(&g_counts[d0], 1);
    if (d1 >= 0) atomicAdd(&g_counts[d1], 1);
    if (d2 >= 0) atomicAdd(&g_counts[d2], 1);
    if (d3 >= 0) atomicAdd(&g_counts[d3], 1);
}

__global__ __launch_bounds__(1024) void scan_local_kernel(int n) {
    __shared__ int sh[1024];
    int t = threadIdx.x;
    int idx = blockIdx.x * 1024 + t;
    int v = (idx < n) ? g_counts[idx] : 0;
    sh[t] = v;
    __syncthreads();
#pragma unroll
    for (int off = 1; off < 1024; off <<= 1) {
        int x = (t >= off) ? sh[t - off] : 0;
        __syncthreads();
        sh[t] += x;
        __syncthreads();
    }
    if (idx < n) g_partial[idx] = sh[t] - v;
    if (t == 1023) g_bsum[blockIdx.x] = sh[1023];
}

// Warp-parallel exclusive scan of <=64 block sums (was 1-thread serial, 5.4us).
__global__ void scan_bsum_kernel(int nb) {
    int lane = threadIdx.x;
    int v0 = (lane < nb)      ? g_bsum[lane]      : 0;
    int v1 = (lane + 32 < nb) ? g_bsum[lane + 32] : 0;
    int s0 = v0;
#pragma unroll
    for (int off = 1; off < 32; off <<= 1) {
        int t = __shfl_up_sync(0xffffffffu, s0, off);
        if (lane >= off) s0 += t;
    }
    int total0 = __shfl_sync(0xffffffffu, s0, 31);
    int s1 = v1;
#pragma unroll
    for (int off = 1; off < 32; off <<= 1) {
        int t = __shfl_up_sync(0xffffffffu, s1, off);
        if (lane >= off) s1 += t;
    }
    s1 += total0;
    if (lane < nb)      g_bsum[lane]      = s0 - v0;   // exclusive
    if (lane + 32 < nb) g_bsum[lane + 32] = s1 - v1;
}

__global__ __launch_bounds__(1024) void scan_add_kernel(int n, int E) {
    int idx = blockIdx.x * 1024 + threadIdx.x;
    if (idx < n) {
        g_row_off[idx] = g_partial[idx] + g_bsum[idx >> 10];
        g_cursor[idx]  = 0;
    } else if (idx == n) {
        g_row_off[n] = E;
    }
}

__global__ void fill_kernel(const int* __restrict__ ei, const float* __restrict__ ew, int E) {
    int e = blockIdx.x * blockDim.x + threadIdx.x;
    if (e >= E) return;
    int s, d;
    load_sd(ei, e, E, g_idx_is64, s, d);
    int pos = g_row_off[d] + atomicAdd(&g_cursor[d], 1);
    g_csr_sw[pos] = make_float2(__int_as_float(s), ew[e]);
}

// ---------------- GEMM1: h[M,128] = x[M,128] @ W1[128,128] (FFMA core) ----------------
__global__ __launch_bounds__(128) void gemm1_kernel(
    const float* __restrict__ x, const float* __restrict__ W, int M)
{
    __shared__ float As[32][64];
    __shared__ float Bs[32][128];

    const int tid = threadIdx.x;
    const int ty  = tid >> 4;
    const int tx  = tid & 15;
    const int rowBase = blockIdx.x * 64;

    float acc[8][8];
#pragma unroll
    for (int i = 0; i < 8; i++)
#pragma unroll
        for (int j = 0; j < 8; j++) acc[i][j] = 0.f;

    for (int kt = 0; kt < IN_C; kt += 32) {
#pragma unroll
        for (int i = 0; i < 4; i++) {
            int idx = tid + i * 128;
            int r   = idx >> 3;
            int kv  = idx & 7;
            int grow = rowBase + r;
            float4 v = make_float4(0.f, 0.f, 0.f, 0.f);
            if (grow < M)
                v = *reinterpret_cast<const float4*>(x + (size_t)grow * IN_C + kt + kv * 4);
            As[kv * 4 + 0][r] = v.x;
            As[kv * 4 + 1][r] = v.y;
            As[kv * 4 + 2][r] = v.z;
            As[kv * 4 + 3][r] = v.w;
        }
#pragma unroll
        for (int i = 0; i < 8; i++) {
            int idx = tid + i * 128;
            int kk  = idx >> 5;
            int nv  = idx & 31;
            *reinterpret_cast<float4*>(&Bs[kk][nv * 4]) =
                *reinterpret_cast<const float4*>(W + (size_t)(kt + kk) * HID_C + nv * 4);
        }
        __syncthreads();

#pragma unroll
        for (int k = 0; k < 32; k++) {
            float a[8], b[8];
            *reinterpret_cast<float4*>(&a[0]) = *reinterpret_cast<float4*>(&As[k][ty * 8]);
            *reinterpret_cast<float4*>(&a[4]) = *reinterpret_cast<float4*>(&As[k][ty * 8 + 4]);
            *reinterpret_cast<float4*>(&b[0]) = *reinterpret_cast<float4*>(&Bs[k][tx * 8]);
            *reinterpret_cast<float4*>(&b[4]) = *reinterpret_cast<float4*>(&Bs[k][tx * 8 + 4]);
#pragma unroll
            for (int i = 0; i < 8; i++)
#pragma unroll
                for (int j = 0; j < 8; j++) acc[i][j] += a[i] * b[j];
        }
        __syncthreads();
    }

#pragma unroll
    for (int i = 0; i < 8; i++) {
        int grow = rowBase + ty * 8 + i;
        if (grow < M) {
#pragma unroll
            for (int j = 0; j < 8; j += 4)
                *reinterpret_cast<float4*>(g_h + (size_t)grow * HID_C + tx * 8 + j) =
                    make_float4(acc[i][j], acc[i][j + 1], acc[i][j + 2], acc[i][j + 3]);
        }
    }
}

// ---------------- gather1: agg[i] = relu(b1 + sum_j w_j*h[src_j]) over [base,end) ----------------
__global__ __launch_bounds__(256) void gather1_kernel(
    const float* __restrict__ b1, int base, int end)
{
    int node = base + ((blockIdx.x * blockDim.x + threadIdx.x) >> 5);
    int lane = threadIdx.x & 31;
    if (node >= end) return;
    int beg = g_row_off[node];
    int fin = g_row_off[node + 1];

    float4 acc0 = make_float4(0.f, 0.f, 0.f, 0.f);
    float4 acc1 = make_float4(0.f, 0.f, 0.f, 0.f);
    float4 acc2 = make_float4(0.f, 0.f, 0.f, 0.f);
    float4 acc3 = make_float4(0.f, 0.f, 0.f, 0.f);
    int j = beg;
    for (; j + 3 < fin; j += 4) {
        float2 p0 = g_csr_sw[j];
        float2 p1 = g_csr_sw[j + 1];
        float2 p2 = g_csr_sw[j + 2];
        float2 p3 = g_csr_sw[j + 3];
        float4 v0 = *(reinterpret_cast<const float4*>(g_h + (size_t)__float_as_int(p0.x) * HID_C) + lane);
        float4 v1 = *(reinterpret_cast<const float4*>(g_h + (size_t)__float_as_int(p1.x) * HID_C) + lane);
        float4 v2 = *(reinterpret_cast<const float4*>(g_h + (size_t)__float_as_int(p2.x) * HID_C) + lane);
        float4 v3 = *(reinterpret_cast<const float4*>(g_h + (size_t)__float_as_int(p3.x) * HID_C) + lane);
        acc0.x += p0.y * v0.x; acc0.y += p0.y * v0.y; acc0.z += p0.y * v0.z; acc0.w += p0.y * v0.w;
        acc1.x += p1.y * v1.x; acc1.y += p1.y * v1.y; acc1.z += p1.y * v1.z; acc1.w += p1.y * v1.w;
        acc2.x += p2.y * v2.x; acc2.y += p2.y * v2.y; acc2.z += p2.y * v2.z; acc2.w += p2.y * v2.w;
        acc3.x += p3.y * v3.x; acc3.y += p3.y * v3.y; acc3.z += p3.y * v3.z; acc3.w += p3.y * v3.w;
    }
    for (; j < fin; j++) {
        float2 p0 = g_csr_sw[j];
        float4 v0 = *(reinterpret_cast<const float4*>(g_h + (size_t)__float_as_int(p0.x) * HID_C) + lane);
        acc0.x += p0.y * v0.x; acc0.y += p0.y * v0.y; acc0.z += p0.y * v0.z; acc0.w += p0.y * v0.w;
    }
    acc0.x += acc1.x + acc2.x + acc3.x;
    acc0.y += acc1.y + acc2.y + acc3.y;
    acc0.z += acc1.z + acc2.z + acc3.z;
    acc0.w += acc1.w + acc2.w + acc3.w;
    float4 bv = *(reinterpret_cast<const float4*>(b1) + lane);
    acc0.x = fmaxf(acc0.x + bv.x, 0.f);
    acc0.y = fmaxf(acc0.y + bv.y, 0.f);
    acc0.z = fmaxf(acc0.z + bv.z, 0.f);
    acc0.w = fmaxf(acc0.w + bv.w, 0.f);
    *(reinterpret_cast<float4*>(g_agg + (size_t)node * HID_C) + lane) = acc0;
}

// ---------------- GEMM2: h2 = agg @ W2 over row range [rowStart,rowEnd) ----------------
__global__ __launch_bounds__(128) void gemm2_kernel(
    const float* __restrict__ W2, int rowStart, int rowEnd)
{
    __shared__ float As[32][128];
    __shared__ float Bs[32][64];

    const int tid = threadIdx.x;
    const int ty  = tid >> 3;
    const int tx  = tid & 7;
    const int rowBase = rowStart + blockIdx.x * 128;

    float acc[8][8];
#pragma unroll
    for (int i = 0; i < 8; i++)
#pragma unroll
        for (int j = 0; j < 8; j++) acc[i][j] = 0.f;

    for (int kt = 0; kt < HID_C; kt += 32) {
#pragma unroll
        for (int i = 0; i < 8; i++) {
            int idx = tid + i * 128;
            int r   = idx >> 3;
            int kv  = idx & 7;
            int grow = rowBase + r;
            float4 v = make_float4(0.f, 0.f, 0.f, 0.f);
            if (grow < rowEnd)
                v = *reinterpret_cast<const float4*>(g_agg + (size_t)grow * HID_C + kt + kv * 4);
            As[kv * 4 + 0][r] = v.x;
            As[kv * 4 + 1][r] = v.y;
            As[kv * 4 + 2][r] = v.z;
            As[kv * 4 + 3][r] = v.w;
        }
#pragma unroll
        for (int i = 0; i < 4; i++) {
            int idx = tid + i * 128;
            int kk  = idx >> 4;
            int nv  = idx & 15;
            *reinterpret_cast<float4*>(&Bs[kk][nv * 4]) =
                *reinterpret_cast<const float4*>(W2 + (size_t)(kt + kk) * OUT_C + nv * 4);
        }
        __syncthreads();

#pragma unroll
        for (int k = 0; k < 32; k++) {
            float a[8], b[8];
            *reinterpret_cast<float4*>(&a[0]) = *reinterpret_cast<float4*>(&As[k][ty * 8]);
            *reinterpret_cast<float4*>(&a[4]) = *reinterpret_cast<float4*>(&As[k][ty * 8 + 4]);
            *reinterpret_cast<float4*>(&b[0]) = *reinterpret_cast<float4*>(&Bs[k][tx * 8]);
            *reinterpret_cast<float4*>(&b[4]) = *reinterpret_cast<float4*>(&Bs[k][tx * 8 + 4]);
#pragma unroll
            for (int i = 0; i < 8; i++)
#pragma unroll
                for (int j = 0; j < 8; j++) acc[i][j] += a[i] * b[j];
        }
        __syncthreads();
    }

#pragma unroll
    for (int i = 0; i < 8; i++) {
        int grow = rowBase + ty * 8 + i;
        if (grow < rowEnd) {
#pragma unroll
            for (int j = 0; j < 8; j += 4)
                *reinterpret_cast<float4*>(g_h2 + (size_t)grow * OUT_C + tx * 8 + j) =
                    make_float4(acc[i][j], acc[i][j + 1], acc[i][j + 2], acc[i][j + 3]);
        }
    }
}

// ---------------- gather2: out[i] = b2 + sum_j h2[src_j], 64 ch ----------------
__global__ __launch_bounds__(256) void gather2_kernel(
    float* __restrict__ out, const float* __restrict__ b2, int n)
{
    int node = (blockIdx.x * blockDim.x + threadIdx.x) >> 5;
    int lane = threadIdx.x & 31;
    if (node >= n) return;
    int beg = g_row_off[node];
    int end = g_row_off[node + 1];

    float2 acc0 = make_float2(0.f, 0.f);
    float2 acc1 = make_float2(0.f, 0.f);
    float2 acc2 = make_float2(0.f, 0.f);
    float2 acc3 = make_float2(0.f, 0.f);
    int j = beg;
    for (; j + 3 < end; j += 4) {
        int s0 = __float_as_int(g_csr_sw[j].x);
        int s1 = __float_as_int(g_csr_sw[j + 1].x);
        int s2 = __float_as_int(g_csr_sw[j + 2].x);
        int s3 = __float_as_int(g_csr_sw[j + 3].x);
        float2 v0 = *(reinterpret_cast<const float2*>(g_h2 + (size_t)s0 * OUT_C) + lane);
        float2 v1 = *(reinterpret_cast<const float2*>(g_h2 + (size_t)s1 * OUT_C) + lane);
        float2 v2 = *(reinterpret_cast<const float2*>(g_h2 + (size_t)s2 * OUT_C) + lane);
        float2 v3 = *(reinterpret_cast<const float2*>(g_h2 + (size_t)s3 * OUT_C) + lane);
        acc0.x += v0.x; acc0.y += v0.y;
        acc1.x += v1.x; acc1.y += v1.y;
        acc2.x += v2.x; acc2.y += v2.y;
        acc3.x += v3.x; acc3.y += v3.y;
    }
    for (; j < end; j++) {
        int s0 = __float_as_int(g_csr_sw[j].x);
        float2 v0 = *(reinterpret_cast<const float2*>(g_h2 + (size_t)s0 * OUT_C) + lane);
        acc0.x += v0.x; acc0.y += v0.y;
    }
    float2 bv = *(reinterpret_cast<const float2*>(b2) + lane);
    acc0.x += acc1.x + acc2.x + acc3.x + bv.x;
    acc0.y += acc1.y + acc2.y + acc3.y + bv.y;
    *(reinterpret_cast<float2*>(out + (size_t)node * OUT_C) + lane) = acc0;
}

// ---------------- launch ----------------
extern "C" void kernel_launch(void* const* d_in, const int* in_sizes, int n_in,
                              void* d_out, int out_size)
{
    const float* x   = (const float*)d_in[0];
    const int*   ei  = (const int*)d_in[1];
    const float* ew  = (const float*)d_in[2];
    const float* W1  = (const float*)d_in[3];
    const float* b1  = (const float*)d_in[4];
    const float* W2  = (const float*)d_in[5];
    const float* b2  = (const float*)d_in[6];
    float*       out = (float*)d_out;

    const int N = in_sizes[0] / IN_C;
    const int E = in_sizes[2];
    const int nScanBlocks = (N + 1023) / 1024;

    static cudaStream_t s_side = nullptr;
    static cudaEvent_t  s_fork = nullptr, s_join = nullptr, s_m = nullptr;
    static cudaEvent_t  s_g[NCHUNK] = {};
    if (s_side == nullptr) {
        cudaStreamCreateWithFlags(&s_side, cudaStreamNonBlocking);
        cudaEventCreateWithFlags(&s_fork, cudaEventDisableTiming);
        cudaEventCreateWithFlags(&s_join, cudaEventDisableTiming);
        cudaEventCreateWithFlags(&s_m,    cudaEventDisableTiming);
        for (int c = 0; c < NCHUNK; c++)
            cudaEventCreateWithFlags(&s_g[c], cudaEventDisableTiming);
    }

    // main: zero counts + detect dtype
    zero_detect_kernel<<<(N + 255) / 256, 256>>>(ei, N);

    // fork: CSR build on side stream, concurrent with gemm1 on main
    cudaEventRecord(s_fork, 0);
    cudaStreamWaitEvent(s_side, s_fork, 0);

    hist_kernel<<<(E / 4 + 255) / 256, 256, 0, s_side>>>(ei, E);
    scan_local_kernel<<<nScanBlocks, 1024, 0, s_side>>>(N);
    scan_bsum_kernel<<<1, 32, 0, s_side>>>(nScanBlocks);
    scan_add_kernel<<<nScanBlocks + 1, 1024, 0, s_side>>>(N, E);
    fill_kernel<<<(E + 255) / 256, 256, 0, s_side>>>(ei, ew, E);
    cudaEventRecord(s_join, s_side);

    // main: dense layer-1 GEMM (independent of CSR)
    gemm1_kernel<<<(N + 63) / 64, 128>>>(x, W1, N);

    // join: gather1 needs both gemm1 (main) and CSR (side)
    cudaStreamWaitEvent(0, s_join, 0);

    // pipelined gather1 (main) / gemm2 (side) over node chunks
    const int chunk = (N + NCHUNK - 1) / NCHUNK;
    for (int c = 0; c < NCHUNK; c++) {
        int s = c * chunk;
        int e = (s + chunk < N) ? s + chunk : N;
        if (s >= e) break;
        int nn = e - s;
        gather1_kernel<<<(nn * 32 + 255) / 256, 256>>>(b1, s, e);
        cudaEventRecord(s_g[c], 0);
        cudaStreamWaitEvent(s_side, s_g[c], 0);
        gemm2_kernel<<<(nn + 127) / 128, 128, 0, s_side>>>(W2, s, e);
    }
    cudaEventRecord(s_m, s_side);
    cudaStreamWaitEvent(0, s_m, 0);

    gather2_kernel<<<(N * 32 + 255) / 256, 256>>>(out, b2, N);
}

// round 9
// speedup vs baseline: 1.5627x; 1.5627x over previous
#include <cuda_runtime.h>
#include <cuda_bf16.h>
#include <mma.h>
#include <cstdint>

using namespace nvcuda;

#define NODES_MAX 50048
#define EDGES_MAX 800000
#define IN_C  128
#define HID_C 128
#define OUT_C 64

// ---------------- device scratch ----------------
__device__ float  g_h   [(size_t)NODES_MAX * HID_C];   // x @ W1
__device__ float  g_agg [(size_t)NODES_MAX * HID_C];   // relu(gather + b1); rows>=N stay 0
__device__ float  g_h2  [(size_t)NODES_MAX * OUT_C];   // agg @ W2
__device__ int    g_idx_is64;

// CSR-by-dst scratch
__device__ int    g_counts [NODES_MAX];
__device__ int    g_partial[NODES_MAX];
__device__ int    g_bsum   [64];
__device__ int    g_row_off[NODES_MAX + 1];
__device__ int    g_cursor [NODES_MAX];
__device__ float2 g_csr_sw [EDGES_MAX];   // .x = src idx (int bits), .y = weight

// ---------------- bf16 split helper ----------------
__device__ __forceinline__ void split_bf16(float v, __nv_bfloat16& h, __nv_bfloat16& l) {
    h = __float2bfloat16(v);
    l = __float2bfloat16(v - __bfloat162float(h));
}

// ================= GEMM1 (wmma bf16-split): h[M,128] = x[M,128] @ W1[128,128] ==========
// 256 threads (8 warps: 2 along M x 4 along N). Single-stage smem, K=128.
// smem: Ahi/Alo [128][136] bf16, Bhi/Blo [128][136] bf16 (B = W1, already K-major).
#define G1_LDA 136
#define G1_AHI 0
#define G1_ALO (G1_AHI + 128 * G1_LDA * 2)
#define G1_BHI (G1_ALO + 128 * G1_LDA * 2)
#define G1_BLO (G1_BHI + 128 * G1_LDA * 2)
#define G1_SMEM (G1_BLO + 128 * G1_LDA * 2)

__global__ __launch_bounds__(256) void gemm1_wmma_kernel(
    const float* __restrict__ x, const float* __restrict__ W, int M)
{
    extern __shared__ char sm[];
    __nv_bfloat16* Ahi = reinterpret_cast<__nv_bfloat16*>(sm + G1_AHI);
    __nv_bfloat16* Alo = reinterpret_cast<__nv_bfloat16*>(sm + G1_ALO);
    __nv_bfloat16* Bhi = reinterpret_cast<__nv_bfloat16*>(sm + G1_BHI);
    __nv_bfloat16* Blo = reinterpret_cast<__nv_bfloat16*>(sm + G1_BLO);

    const int tid = threadIdx.x;
    const int wid = tid >> 5;
    const int rowBase = blockIdx.x * 128;

    // A: x[rowBase..rowBase+127][0..127] -> split (guarded rows)
    for (int i = 0; i < 16; i++) {
        int q  = tid + i * 256;      // 0..4095 float4s
        int r  = q >> 5;             // row
        int c4 = q & 31;             // float4 within row
        float4 v = make_float4(0.f, 0.f, 0.f, 0.f);
        int grow = rowBase + r;
        if (grow < M)
            v = *reinterpret_cast<const float4*>(x + (size_t)grow * IN_C + c4 * 4);
        __nv_bfloat16 h0, h1, h2, h3, l0, l1, l2, l3;
        split_bf16(v.x, h0, l0); split_bf16(v.y, h1, l1);
        split_bf16(v.z, h2, l2); split_bf16(v.w, h3, l3);
        int o = r * G1_LDA + c4 * 4;
        Ahi[o] = h0; Ahi[o + 1] = h1; Ahi[o + 2] = h2; Ahi[o + 3] = h3;
        Alo[o] = l0; Alo[o + 1] = l1; Alo[o + 2] = l2; Alo[o + 3] = l3;
    }
    // B: W1[k][n] (row-major K x N) -> split (unguarded, full 128x128)
    for (int i = 0; i < 16; i++) {
        int q  = tid + i * 256;
        int r  = q >> 5;
        int c4 = q & 31;
        float4 v = *reinterpret_cast<const float4*>(W + (size_t)r * HID_C + c4 * 4);
        __nv_bfloat16 h0, h1, h2, h3, l0, l1, l2, l3;
        split_bf16(v.x, h0, l0); split_bf16(v.y, h1, l1);
        split_bf16(v.z, h2, l2); split_bf16(v.w, h3, l3);
        int o = r * G1_LDA + c4 * 4;
        Bhi[o] = h0; Bhi[o + 1] = h1; Bhi[o + 2] = h2; Bhi[o + 3] = h3;
        Blo[o] = l0; Blo[o + 1] = l1; Blo[o + 2] = l2; Blo[o + 3] = l3;
    }
    __syncthreads();

    const int warp_m = wid >> 2;     // 0..1 (64 rows each)
    const int warp_n = wid & 3;      // 0..3 (32 cols each)

    wmma::fragment<wmma::accumulator, 16, 16, 16, float> acc[4][2];
#pragma unroll
    for (int mi = 0; mi < 4; mi++)
#pragma unroll
        for (int ni = 0; ni < 2; ni++) wmma::fill_fragment(acc[mi][ni], 0.f);

#pragma unroll
    for (int ks = 0; ks < 8; ks++) {
        int k0 = ks * 16;
        wmma::fragment<wmma::matrix_b, 16, 16, 16, __nv_bfloat16, wmma::row_major> bh[2], bl[2];
#pragma unroll
        for (int ni = 0; ni < 2; ni++) {
            wmma::load_matrix_sync(bh[ni], Bhi + k0 * G1_LDA + warp_n * 32 + ni * 16, G1_LDA);
            wmma::load_matrix_sync(bl[ni], Blo + k0 * G1_LDA + warp_n * 32 + ni * 16, G1_LDA);
        }
#pragma unroll
        for (int mi = 0; mi < 4; mi++) {
            int r0 = warp_m * 64 + mi * 16;
            wmma::fragment<wmma::matrix_a, 16, 16, 16, __nv_bfloat16, wmma::row_major> ah, al;
            wmma::load_matrix_sync(ah, Ahi + r0 * G1_LDA + k0, G1_LDA);
            wmma::load_matrix_sync(al, Alo + r0 * G1_LDA + k0, G1_LDA);
#pragma unroll
            for (int ni = 0; ni < 2; ni++) {
                wmma::mma_sync(acc[mi][ni], ah, bh[ni], acc[mi][ni]);
                wmma::mma_sync(acc[mi][ni], ah, bl[ni], acc[mi][ni]);
                wmma::mma_sync(acc[mi][ni], al, bh[ni], acc[mi][ni]);
            }
        }
    }

    // store (rows < NODES_MAX by construction: 391*128 = 50048)
#pragma unroll
    for (int mi = 0; mi < 4; mi++) {
        int r0 = rowBase + warp_m * 64 + mi * 16;
#pragma unroll
        for (int ni = 0; ni < 2; ni++) {
            wmma::store_matrix_sync(g_h + (size_t)r0 * HID_C + warp_n * 32 + ni * 16,
                                    acc[mi][ni], HID_C, wmma::mem_row_major);
        }
    }
}

// ================= GEMM2 (wmma bf16-split): h2[M,64] = agg[M,128] @ W2[128,64] =========
// 256 threads (8 warps: 4 along M x 2 along N).
#define G2_LDA 136
#define G2_LDB 72
#define G2_AHI 0
#define G2_ALO (G2_AHI + 128 * G2_LDA * 2)
#define G2_BHI (G2_ALO + 128 * G2_LDA * 2)
#define G2_BLO (G2_BHI + 128 * G2_LDB * 2)
#define G2_SMEM (G2_BLO + 128 * G2_LDB * 2)

__global__ __launch_bounds__(256) void gemm2_wmma_kernel(const float* __restrict__ W2)
{
    extern __shared__ char sm[];
    __nv_bfloat16* Ahi = reinterpret_cast<__nv_bfloat16*>(sm + G2_AHI);
    __nv_bfloat16* Alo = reinterpret_cast<__nv_bfloat16*>(sm + G2_ALO);
    __nv_bfloat16* Bhi = reinterpret_cast<__nv_bfloat16*>(sm + G2_BHI);
    __nv_bfloat16* Blo = reinterpret_cast<__nv_bfloat16*>(sm + G2_BLO);

    const int tid = threadIdx.x;
    const int wid = tid >> 5;
    const int rowBase = blockIdx.x * 128;

    // A: g_agg rows (scratch; rows >= N are zero-initialized and never written)
    for (int i = 0; i < 16; i++) {
        int q  = tid + i * 256;
        int r  = q >> 5;
        int c4 = q & 31;
        float4 v = *reinterpret_cast<const float4*>(g_agg + (size_t)(rowBase + r) * HID_C + c4 * 4);
        __nv_bfloat16 h0, h1, h2, h3, l0, l1, l2, l3;
        split_bf16(v.x, h0, l0); split_bf16(v.y, h1, l1);
        split_bf16(v.z, h2, l2); split_bf16(v.w, h3, l3);
        int o = r * G2_LDA + c4 * 4;
        Ahi[o] = h0; Ahi[o + 1] = h1; Ahi[o + 2] = h2; Ahi[o + 3] = h3;
        Alo[o] = l0; Alo[o + 1] = l1; Alo[o + 2] = l2; Alo[o + 3] = l3;
    }
    // B: W2[k][n], 128x64
    for (int i = 0; i < 8; i++) {
        int q  = tid + i * 256;      // 0..2047 float4s
        int r  = q >> 4;             // 16 float4 per row
        int c4 = q & 15;
        float4 v = *reinterpret_cast<const float4*>(W2 + (size_t)r * OUT_C + c4 * 4);
        __nv_bfloat16 h0, h1, h2, h3, l0, l1, l2, l3;
        split_bf16(v.x, h0, l0); split_bf16(v.y, h1, l1);
        split_bf16(v.z, h2, l2); split_bf16(v.w, h3, l3);
        int o = r * G2_LDB + c4 * 4;
        Bhi[o] = h0; Bhi[o + 1] = h1; Bhi[o + 2] = h2; Bhi[o + 3] = h3;
        Blo[o] = l0; Blo[o + 1] = l1; Blo[o + 2] = l2; Blo[o + 3] = l3;
    }
    __syncthreads();

    const int warp_m = wid >> 1;     // 0..3 (32 rows each)
    const int warp_n = wid & 1;      // 0..1 (32 cols each)

    wmma::fragment<wmma::accumulator, 16, 16, 16, float> acc[2][2];
#pragma unroll
    for (int mi = 0; mi < 2; mi++)
#pragma unroll
        for (int ni = 0; ni < 2; ni++) wmma::fill_fragment(acc[mi][ni], 0.f);

#pragma unroll
    for (int ks = 0; ks < 8; ks++) {
        int k0 = ks * 16;
        wmma::fragment<wmma::matrix_b, 16, 16, 16, __nv_bfloat16, wmma::row_major> bh[2], bl[2];
#pragma unroll
        for (int ni = 0; ni < 2; ni++) {
            wmma::load_matrix_sync(bh[ni], Bhi + k0 * G2_LDB + warp_n * 32 + ni * 16, G2_LDB);
            wmma::load_matrix_sync(bl[ni], Blo + k0 * G2_LDB + warp_n * 32 + ni * 16, G2_LDB);
        }
#pragma unroll
        for (int mi = 0; mi < 2; mi++) {
            int r0 = warp_m * 32 + mi * 16;
            wmma::fragment<wmma::matrix_a, 16, 16, 16, __nv_bfloat16, wmma::row_major> ah, al;
            wmma::load_matrix_sync(ah, Ahi + r0 * G2_LDA + k0, G2_LDA);
            wmma::load_matrix_sync(al, Alo + r0 * G2_LDA + k0, G2_LDA);
#pragma unroll
            for (int ni = 0; ni < 2; ni++) {
                wmma::mma_sync(acc[mi][ni], ah, bh[ni], acc[mi][ni]);
                wmma::mma_sync(acc[mi][ni], ah, bl[ni], acc[mi][ni]);
                wmma::mma_sync(acc[mi][ni], al, bh[ni], acc[mi][ni]);
            }
        }
    }

#pragma unroll
    for (int mi = 0; mi < 2; mi++) {
        int r0 = rowBase + warp_m * 32 + mi * 16;
#pragma unroll
        for (int ni = 0; ni < 2; ni++) {
            wmma::store_matrix_sync(g_h2 + (size_t)r0 * OUT_C + warp_n * 32 + ni * 16,
                                    acc[mi][ni], OUT_C, wmma::mem_row_major);
        }
    }
}

// ---------------- zero counts + detect idx dtype (merged) ----------------
__global__ void zero_detect_kernel(const int* __restrict__ ei_words, int n) {
    int i = blockIdx.x * blockDim.x + threadIdx.x;
    if (i < n) g_counts[i] = 0;
    if (blockIdx.x == 0 && threadIdx.x < 32) {
        int lane = threadIdx.x;
        int bad = 0;
        for (int k = lane; k < 1024; k += 32)
            if (ei_words[2 * k + 1] != 0) bad = 1;
        bad = __any_sync(0xffffffffu, bad);
        if (lane == 0) g_idx_is64 = bad ? 0 : 1;
    }
}

__device__ __forceinline__ void load_sd(const int* __restrict__ ei, int e, int E,
                                        int is64, int& s, int& d) {
    if (is64) { s = ei[2 * e]; d = ei[2 * E + 2 * e]; }
    else      { s = ei[e];     d = ei[E + e]; }
}
__device__ __forceinline__ int load_d(const int* __restrict__ ei, int e, int E, int is64) {
    return is64 ? ei[2 * E + 2 * e] : ei[E + e];
}

// ---------------- CSR build ----------------
__global__ void hist_kernel(const int* __restrict__ ei, int E) {
    int base = (blockIdx.x * blockDim.x + threadIdx.x) * 4;
    int is64 = g_idx_is64;
    int d0 = -1, d1 = -1, d2 = -1, d3 = -1;
    if (base + 0 < E) d0 = load_d(ei, base + 0, E, is64);
    if (base + 1 < E) d1 = load_d(ei, base + 1, E, is64);
    if (base + 2 < E) d2 = load_d(ei, base + 2, E, is64);
    if (base + 3 < E) d3 = load_d(ei, base + 3, E, is64);
    if (d0 >= 0) atomicAdd(&g_counts[d0], 1);
    if (d1 >= 0) atomicAdd(&g_counts[d1], 1);
    if (d2 >= 0) atomicAdd(&g_counts[d2], 1);
    if (d3 >= 0) atomicAdd(&g_counts[d3], 1);
}

__global__ __launch_bounds__(1024) void scan_local_kernel(int n) {
    __shared__ int sh[1024];
    int t = threadIdx.x;
    int idx = blockIdx.x * 1024 + t;
    int v = (idx < n) ? g_counts[idx] : 0;
    sh[t] = v;
    __syncthreads();
#pragma unroll
    for (int off = 1; off < 1024; off <<= 1) {
        int xv = (t >= off) ? sh[t - off] : 0;
        __syncthreads();
        sh[t] += xv;
        __syncthreads();
    }
    if (idx < n) g_partial[idx] = sh[t] - v;
    if (t == 1023) g_bsum[blockIdx.x] = sh[1023];
}

__global__ void scan_bsum_kernel(int nb) {
    int lane = threadIdx.x;
    int v0 = (lane < nb)      ? g_bsum[lane]      : 0;
    int v1 = (lane + 32 < nb) ? g_bsum[lane + 32] : 0;
    int s0 = v0;
#pragma unroll
    for (int off = 1; off < 32; off <<= 1) {
        int t = __shfl_up_sync(0xffffffffu, s0, off);
        if (lane >= off) s0 += t;
    }
    int total0 = __shfl_sync(0xffffffffu, s0, 31);
    int s1 = v1;
#pragma unroll
    for (int off = 1; off < 32; off <<= 1) {
        int t = __shfl_up_sync(0xffffffffu, s1, off);
        if (lane >= off) s1 += t;
    }
    s1 += total0;
    if (lane < nb)      g_bsum[lane]      = s0 - v0;
    if (lane + 32 < nb) g_bsum[lane + 32] = s1 - v1;
}

__global__ __launch_bounds__(1024) void scan_add_kernel(int n, int E) {
    int idx = blockIdx.x * 1024 + threadIdx.x;
    if (idx < n) {
        g_row_off[idx] = g_partial[idx] + g_bsum[idx >> 10];
        g_cursor[idx]  = 0;
    } else if (idx == n) {
        g_row_off[n] = E;
    }
}

__global__ void fill_kernel(const int* __restrict__ ei, const float* __restrict__ ew, int E) {
    int e = blockIdx.x * blockDim.x + threadIdx.x;
    if (e >= E) return;
    int s, d;
    load_sd(ei, e, E, g_idx_is64, s, d);
    int pos = g_row_off[d] + atomicAdd(&g_cursor[d], 1);
    g_csr_sw[pos] = make_float2(__int_as_float(s), ew[e]);
}

// ---------------- gather1: agg[i] = relu(b1 + sum_j w_j*h[src_j]), 128 ch ----------------
__global__ __launch_bounds__(256) void gather1_kernel(const float* __restrict__ b1, int n)
{
    int node = (blockIdx.x * blockDim.x + threadIdx.x) >> 5;
    int lane = threadIdx.x & 31;
    if (node >= n) return;
    int beg = g_row_off[node];
    int fin = g_row_off[node + 1];

    float4 acc0 = make_float4(0.f, 0.f, 0.f, 0.f);
    float4 acc1 = make_float4(0.f, 0.f, 0.f, 0.f);
    float4 acc2 = make_float4(0.f, 0.f, 0.f, 0.f);
    float4 acc3 = make_float4(0.f, 0.f, 0.f, 0.f);
    int j = beg;
    for (; j + 3 < fin; j += 4) {
        float2 p0 = g_csr_sw[j];
        float2 p1 = g_csr_sw[j + 1];
        float2 p2 = g_csr_sw[j + 2];
        float2 p3 = g_csr_sw[j + 3];
        float4 v0 = *(reinterpret_cast<const float4*>(g_h + (size_t)__float_as_int(p0.x) * HID_C) + lane);
        float4 v1 = *(reinterpret_cast<const float4*>(g_h + (size_t)__float_as_int(p1.x) * HID_C) + lane);
        float4 v2 = *(reinterpret_cast<const float4*>(g_h + (size_t)__float_as_int(p2.x) * HID_C) + lane);
        float4 v3 = *(reinterpret_cast<const float4*>(g_h + (size_t)__float_as_int(p3.x) * HID_C) + lane);
        acc0.x += p0.y * v0.x; acc0.y += p0.y * v0.y; acc0.z += p0.y * v0.z; acc0.w += p0.y * v0.w;
        acc1.x += p1.y * v1.x; acc1.y += p1.y * v1.y; acc1.z += p1.y * v1.z; acc1.w += p1.y * v1.w;
        acc2.x += p2.y * v2.x; acc2.y += p2.y * v2.y; acc2.z += p2.y * v2.z; acc2.w += p2.y * v2.w;
        acc3.x += p3.y * v3.x; acc3.y += p3.y * v3.y; acc3.z += p3.y * v3.z; acc3.w += p3.y * v3.w;
    }
    for (; j < fin; j++) {
        float2 p0 = g_csr_sw[j];
        float4 v0 = *(reinterpret_cast<const float4*>(g_h + (size_t)__float_as_int(p0.x) * HID_C) + lane);
        acc0.x += p0.y * v0.x; acc0.y += p0.y * v0.y; acc0.z += p0.y * v0.z; acc0.w += p0.y * v0.w;
    }
    acc0.x += acc1.x + acc2.x + acc3.x;
    acc0.y += acc1.y + acc2.y + acc3.y;
    acc0.z += acc1.z + acc2.z + acc3.z;
    acc0.w += acc1.w + acc2.w + acc3.w;
    float4 bv = *(reinterpret_cast<const float4*>(b1) + lane);
    acc0.x = fmaxf(acc0.x + bv.x, 0.f);
    acc0.y = fmaxf(acc0.y + bv.y, 0.f);
    acc0.z = fmaxf(acc0.z + bv.z, 0.f);
    acc0.w = fmaxf(acc0.w + bv.w, 0.f);
    *(reinterpret_cast<float4*>(g_agg + (size_t)node * HID_C) + lane) = acc0;
}

// ---------------- gather2: out[i] = b2 + sum_j h2[src_j], 64 ch ----------------
__global__ __launch_bounds__(256) void gather2_kernel(
    float* __restrict__ out, const float* __restrict__ b2, int n)
{
    int node = (blockIdx.x * blockDim.x + threadIdx.x) >> 5;
    int lane = threadIdx.x & 31;
    if (node >= n) return;
    int beg = g_row_off[node];
    int end = g_row_off[node + 1];

    float2 acc0 = make_float2(0.f, 0.f);
    float2 acc1 = make_float2(0.f, 0.f);
    float2 acc2 = make_float2(0.f, 0.f);
    float2 acc3 = make_float2(0.f, 0.f);
    int j = beg;
    for (; j + 3 < end; j += 4) {
        int s0 = __float_as_int(g_csr_sw[j].x);
        int s1 = __float_as_int(g_csr_sw[j + 1].x);
        int s2 = __float_as_int(g_csr_sw[j + 2].x);
        int s3 = __float_as_int(g_csr_sw[j + 3].x);
        float2 v0 = *(reinterpret_cast<const float2*>(g_h2 + (size_t)s0 * OUT_C) + lane);
        float2 v1 = *(reinterpret_cast<const float2*>(g_h2 + (size_t)s1 * OUT_C) + lane);
        float2 v2 = *(reinterpret_cast<const float2*>(g_h2 + (size_t)s2 * OUT_C) + lane);
        float2 v3 = *(reinterpret_cast<const float2*>(g_h2 + (size_t)s3 * OUT_C) + lane);
        acc0.x += v0.x; acc0.y += v0.y;
        acc1.x += v1.x; acc1.y += v1.y;
        acc2.x += v2.x; acc2.y += v2.y;
        acc3.x += v3.x; acc3.y += v3.y;
    }
    for (; j < end; j++) {
        int s0 = __float_as_int(g_csr_sw[j].x);
        float2 v0 = *(reinterpret_cast<const float2*>(g_h2 + (size_t)s0 * OUT_C) + lane);
        acc0.x += v0.x; acc0.y += v0.y;
    }
    float2 bv = *(reinterpret_cast<const float2*>(b2) + lane);
    acc0.x += acc1.x + acc2.x + acc3.x + bv.x;
    acc0.y += acc1.y + acc2.y + acc3.y + bv.y;
    *(reinterpret_cast<float2*>(out + (size_t)node * OUT_C) + lane) = acc0;
}

// ---------------- launch ----------------
extern "C" void kernel_launch(void* const* d_in, const int* in_sizes, int n_in,
                              void* d_out, int out_size)
{
    const float* x   = (const float*)d_in[0];
    const int*   ei  = (const int*)d_in[1];
    const float* ew  = (const float*)d_in[2];
    const float* W1  = (const float*)d_in[3];
    const float* b1  = (const float*)d_in[4];
    const float* W2  = (const float*)d_in[5];
    const float* b2  = (const float*)d_in[6];
    float*       out = (float*)d_out;

    const int N = in_sizes[0] / IN_C;
    const int E = in_sizes[2];
    const int nScanBlocks = (N + 1023) / 1024;
    const int nGemmBlocks = (N + 127) / 128;   // 391 -> covers exactly NODES_MAX rows

    static cudaStream_t s_side = nullptr;
    static cudaEvent_t  s_fork = nullptr, s_join = nullptr;
    if (s_side == nullptr) {
        cudaStreamCreateWithFlags(&s_side, cudaStreamNonBlocking);
        cudaEventCreateWithFlags(&s_fork, cudaEventDisableTiming);
        cudaEventCreateWithFlags(&s_join, cudaEventDisableTiming);
        cudaFuncSetAttribute(gemm1_wmma_kernel,
                             cudaFuncAttributeMaxDynamicSharedMemorySize, G1_SMEM);
        cudaFuncSetAttribute(gemm2_wmma_kernel,
                             cudaFuncAttributeMaxDynamicSharedMemorySize, G2_SMEM);
    }

    // main: zero counts + detect dtype
    zero_detect_kernel<<<(N + 255) / 256, 256>>>(ei, N);

    // fork: CSR build on side stream, concurrent with gemm1 on main
    cudaEventRecord(s_fork, 0);
    cudaStreamWaitEvent(s_side, s_fork, 0);

    hist_kernel<<<(E / 4 + 255) / 256, 256, 0, s_side>>>(ei, E);
    scan_local_kernel<<<nScanBlocks, 1024, 0, s_side>>>(N);
    scan_bsum_kernel<<<1, 32, 0, s_side>>>(nScanBlocks);
    scan_add_kernel<<<nScanBlocks + 1, 1024, 0, s_side>>>(N, E);
    fill_kernel<<<(E + 255) / 256, 256, 0, s_side>>>(ei, ew, E);
    cudaEventRecord(s_join, s_side);

    // main: tensor-core (wmma) layer-1 GEMM
    gemm1_wmma_kernel<<<nGemmBlocks, 256, G1_SMEM>>>(x, W1, N);

    // join
    cudaStreamWaitEvent(0, s_join, 0);

    gather1_kernel<<<(N * 32 + 255) / 256, 256>>>(b1, N);
    gemm2_wmma_kernel<<<nGemmBlocks, 256, G2_SMEM>>>(W2);
    gather2_kernel<<<(N * 32 + 255) / 256, 256>>>(out, b2, N);
}